// round 17
// baseline (speedup 1.0000x reference)
#include <cuda_runtime.h>
#include <cuda_fp16.h>
#include <math.h>
#include <stdint.h>

// Problem constants
#define BSZ   32
#define TD    64
#define TEC   128
#define EDIM  256
#define HDIM  512
#define G4    2048
#define VOC   32000
#define M_BT  2048

// Unified HMMA GEMM tiling: 128x128, 2-stage, 2 CTAs/SM
#define BM    128
#define BN    128
#define BK    64
#define KDIM  512
#define ROWB  144
#define SA_BYTES (BM * ROWB)
#define SB_BYTES (BN * ROWB)
#define STAGE    (SA_BYTES + SB_BYTES)
#define SM_TOTAL (2 * STAGE)

// Persistent LSTM: 32 worker CTAs x 512 threads (16 units each) + 116 converters
#define LCTA  32
#define TOTCTA 148
#define NCVT  (TOTCTA - LCTA)
#define SAROW 1040
#define SMH   (64 * SAROW)                     // 66560 (after 64-row W tile)
#define SMG   (SMH + 32 * SAROW)               // 99840
#define STEP_SMEM (SMG + 2 * 64 * 33 * 4)      // 116736

// HMMA attention kernel
#define AT_ENC 0
#define AT_H   (128 * SAROW)
#define AT_SC  (AT_H + 32 * SAROW)
#define AT_P   (AT_SC + 32 * 132 * 4)
#define ATN_SMEM (AT_P + 32 * 136 * 2)

// Init kernel grid sections (LSTM-critical only)
#define NB_WIH  512
#define NB_WHH  1024
#define NB_BIAS 8
#define NB_H0   64
#define NB_EMB  2048
#define NB_INIT (NB_WIH + NB_WHH + NB_BIAS + NB_H0 + NB_EMB)

// Scratch
__device__ float g_bias[G4];
__device__ float g_xihp[(size_t)TD * G4 * BSZ];
__device__ float g_c   [BSZ * HDIM];
__device__ unsigned g_bar;
__device__ __align__(16) __half g_hsh[(size_t)(TD + 1) * BSZ * HDIM];
__device__ __align__(16) __half g_ench[(size_t)BSZ * TEC * HDIM];
__device__ __align__(16) __half g_embh[M_BT * EDIM];
__device__ __align__(16) __half g_Wihh[(size_t)G4 * EDIM];
__device__ __align__(16) __half g_cath[(size_t)M_BT * 2 * HDIM];
__device__ __align__(16) __half g_attWh[(size_t)HDIM * 2 * HDIM];
__device__ __align__(16) __half g_Whp[(size_t)G4 * HDIM];
__device__ __align__(16) __half g_Ah[(size_t)M_BT * KDIM];
__device__ __align__(16) __half g_Bh[(size_t)VOC * KDIM];

__device__ __forceinline__ float sigf(float x) { return 1.0f / (1.0f + expf(-x)); }

__device__ __forceinline__ uint32_t smem_u32(const void* p) {
    uint32_t a;
    asm("{ .reg .u64 t; cvta.to.shared.u64 t, %1; cvt.u32.u64 %0, t; }" : "=r"(a) : "l"(p));
    return a;
}

__device__ __forceinline__ void cvt4(const float* src, __half* dst) {
    float4 x = *(const float4*)src;
    __half h[4] = {__float2half(x.x), __float2half(x.y),
                   __float2half(x.z), __float2half(x.w)};
    *(uint2*)dst = *(uint2*)h;
}

// ---------------------------------------------------------------------------
__global__ void k_init(const float* __restrict__ Wih, const float* __restrict__ Whh,
                       const float* __restrict__ bih, const float* __restrict__ bhh,
                       const float* __restrict__ h0, const int* __restrict__ decX,
                       const float* __restrict__ embW) {
    int blk = blockIdx.x, tid = threadIdx.x;
    if (blk < NB_WIH) {
        size_t i4 = (size_t)blk * 256 + tid;
        cvt4(Wih + i4 * 4, g_Wihh + i4 * 4);
        return;
    }
    blk -= NB_WIH;
    if (blk < NB_WHH) {
        size_t i4 = (size_t)blk * 256 + tid;
        size_t e = i4 * 4;
        int rp = (int)(e >> 9), k = (int)(e & 511);
        int u = rp >> 2, g = rp & 3;
        cvt4(Whh + (size_t)(g * HDIM + u) * HDIM + k, g_Whp + (size_t)rp * HDIM + k);
        return;
    }
    blk -= NB_WHH;
    if (blk < NB_BIAS) {
        int i = blk * 256 + tid;
        g_bias[i] = bih[i] + bhh[i];
        if (i == 0) g_bar = 0u;
        return;
    }
    blk -= NB_BIAS;
    if (blk < NB_H0) {
        int i = blk * 256 + tid;
        g_hsh[i] = __float2half(h0[i]);
        return;
    }
    blk -= NB_H0;
    {
        int m = blk, e = tid;
        int b = m & (BSZ - 1), t = m >> 5;
        int tok = decX[b * TD + t];
        g_embh[m * EDIM + e] = __float2half(embW[tok * EDIM + e]);
    }
}

// ---------------------------------------------------------------------------
// Unified fp16 HMMA GEMM (unchanged from R14)
__global__ __launch_bounds__(256, 2)
void k_hgemm2(const __half* __restrict__ A, const __half* __restrict__ B,
              const float* __restrict__ bias, float* __restrict__ C,
              int K, int nI, int ldc, int mode) {
    extern __shared__ char smem[];
    uint32_t sb = smem_u32(smem);
    int tid = threadIdx.x;
    int wid = tid >> 5, lane = tid & 31;
    int wm = wid & 3, wn = wid >> 2;
    int m0 = blockIdx.x * BM, n0 = blockIdx.y * BN;

    const __half* gA0 = A + (size_t)m0 * K;
    const __half* gB0 = B + (size_t)n0 * K;

    auto load_stage = [&](int kt, int s) {
        uint32_t sa = sb + s * STAGE;
        const __half* gA = gA0 + kt * BK;
#pragma unroll
        for (int r4 = 0; r4 < 4; r4++) {
            int li = r4 * 256 + tid;
            int row = li >> 3, seg = li & 7;
            uint32_t dst = sa + row * ROWB + seg * 16;
            const void* src = gA + (size_t)row * K + seg * 8;
            asm volatile("cp.async.cg.shared.global [%0], [%1], 16;" :: "r"(dst), "l"(src));
        }
        uint32_t sbB = sa + SA_BYTES;
        const __half* gB = gB0 + kt * BK;
#pragma unroll
        for (int r4 = 0; r4 < 4; r4++) {
            int li = r4 * 256 + tid;
            int row = li >> 3, seg = li & 7;
            uint32_t dst = sbB + row * ROWB + seg * 16;
            const void* src = gB + (size_t)row * K + seg * 8;
            asm volatile("cp.async.cg.shared.global [%0], [%1], 16;" :: "r"(dst), "l"(src));
        }
        asm volatile("cp.async.commit_group;" ::: "memory");
    };

    float acc[2][8][4];
#pragma unroll
    for (int i = 0; i < 2; i++)
#pragma unroll
        for (int j = 0; j < 8; j++)
#pragma unroll
            for (int q = 0; q < 4; q++) acc[i][j][q] = 0.0f;

    load_stage(0, 0);

    for (int kt = 0; kt < nI; kt++) {
        asm volatile("cp.async.wait_group 0;" ::: "memory");
        __syncthreads();
        if (kt + 1 < nI) load_stage(kt + 1, (kt + 1) & 1);

        uint32_t sa = sb + (kt & 1) * STAGE;
        uint32_t sB = sa + SA_BYTES;
#pragma unroll
        for (int kk = 0; kk < 4; kk++) {
            uint32_t a[2][4], b[4][4];
#pragma unroll
            for (int i = 0; i < 2; i++) {
                int row = wm * 32 + i * 16 + (lane & 15);
                int ko = kk * 16 + ((lane >> 4) << 3);
                uint32_t ad = sa + row * ROWB + ko * 2;
                asm volatile("ldmatrix.sync.aligned.m8n8.x4.shared.b16 {%0,%1,%2,%3}, [%4];"
                             : "=r"(a[i][0]), "=r"(a[i][1]), "=r"(a[i][2]), "=r"(a[i][3])
                             : "r"(ad));
            }
#pragma unroll
            for (int j2 = 0; j2 < 4; j2++) {
                int nrow = wn * 64 + j2 * 16 + (lane & 7) + (((lane >> 4) & 1) << 3);
                int ko = kk * 16 + (((lane >> 3) & 1) << 3);
                uint32_t bd = sB + nrow * ROWB + ko * 2;
                asm volatile("ldmatrix.sync.aligned.m8n8.x4.shared.b16 {%0,%1,%2,%3}, [%4];"
                             : "=r"(b[j2][0]), "=r"(b[j2][1]), "=r"(b[j2][2]), "=r"(b[j2][3])
                             : "r"(bd));
            }
#pragma unroll
            for (int i = 0; i < 2; i++)
#pragma unroll
                for (int j2 = 0; j2 < 4; j2++) {
                    asm volatile(
                        "mma.sync.aligned.m16n8k16.row.col.f32.f16.f16.f32 "
                        "{%0,%1,%2,%3}, {%4,%5,%6,%7}, {%8,%9}, {%0,%1,%2,%3};"
                        : "+f"(acc[i][2*j2][0]), "+f"(acc[i][2*j2][1]),
                          "+f"(acc[i][2*j2][2]), "+f"(acc[i][2*j2][3])
                        : "r"(a[i][0]), "r"(a[i][1]), "r"(a[i][2]), "r"(a[i][3]),
                          "r"(b[j2][0]), "r"(b[j2][1]));
                    asm volatile(
                        "mma.sync.aligned.m16n8k16.row.col.f32.f16.f16.f32 "
                        "{%0,%1,%2,%3}, {%4,%5,%6,%7}, {%8,%9}, {%0,%1,%2,%3};"
                        : "+f"(acc[i][2*j2+1][0]), "+f"(acc[i][2*j2+1][1]),
                          "+f"(acc[i][2*j2+1][2]), "+f"(acc[i][2*j2+1][3])
                        : "r"(a[i][0]), "r"(a[i][1]), "r"(a[i][2]), "r"(a[i][3]),
                          "r"(b[j2][2]), "r"(b[j2][3]));
                }
        }
        __syncthreads();
    }

#pragma unroll
    for (int j = 0; j < 8; j++) {
        int ncol = n0 + wn * 64 + j * 8 + (lane & 3) * 2;
        float b0 = bias[ncol], b1 = bias[ncol + 1];
#pragma unroll
        for (int i = 0; i < 2; i++) {
            int mr0 = m0 + wm * 32 + i * 16 + (lane >> 2);
#pragma unroll
            for (int h = 0; h < 2; h++) {
                int mrow = mr0 + h * 8;
                float v0 = acc[i][j][2*h + 0] + b0;
                float v1 = acc[i][j][2*h + 1] + b1;
                if (mode == 0) {
                    int tt = mrow >> 5, bb2 = mrow & 31;
                    int rp0 = ((ncol & 511) << 2) | (ncol >> 9);
                    int rp1 = (((ncol + 1) & 511) << 2) | ((ncol + 1) >> 9);
                    g_xihp[((size_t)tt * G4 + rp0) * 32 + bb2] = v0;
                    g_xihp[((size_t)tt * G4 + rp1) * 32 + bb2] = v1;
                } else if (mode == 1) {
                    __half2 hv = __floats2half2_rn(tanhf(v0), tanhf(v1));
                    *(__half2*)(g_Ah + (size_t)mrow * KDIM + ncol) = hv;
                } else {
                    float2 v = {v0, v1};
                    *(float2*)(C + (size_t)mrow * ldc + ncol) = v;
                }
            }
        }
    }
}

// ---------------------------------------------------------------------------
// Persistent fused LSTM: 32 worker CTAs x 512 threads (16 units each);
// CTAs [32,148) = free-rider converters. Same kk-half partial-sum order
// as R14 (bit-identical arithmetic).
__global__ __launch_bounds__(512, 1)
void k_lstm_p(const float* __restrict__ c0, float* __restrict__ out,
              const float* __restrict__ fcW, const float* __restrict__ attW,
              const float* __restrict__ enc) {
    int tid = threadIdx.x;
    if (blockIdx.x >= LCTA) {
        size_t gtid = (size_t)(blockIdx.x - LCTA) * 512 + tid;
        const size_t NTH = (size_t)NCVT * 512;
        for (size_t i = gtid; i < (size_t)VOC * HDIM / 4; i += NTH)
            cvt4(fcW + i * 4, g_Bh + i * 4);
        for (size_t i = gtid; i < (size_t)HDIM * 2 * HDIM / 4; i += NTH)
            cvt4(attW + i * 4, g_attWh + i * 4);
        for (size_t i = gtid; i < (size_t)BSZ * TEC * HDIM / 4; i += NTH)
            cvt4(enc + i * 4, g_ench + i * 4);
        return;
    }

    extern __shared__ char sm[];
    uint32_t sb = smem_u32(sm);
    int w = tid >> 5, lane = tid & 31;
    int jt = blockIdx.x;

    // W tile: 64 permuted rows (16 units x 4 gates) — persists all 64 steps
    const __half* Wp = g_Whp + (size_t)(jt * 64) * HDIM;
#pragma unroll
    for (int p = 0; p < 8; p++) {
        int idx = p * 512 + tid;                 // 4096 segs: 64 rows x 64
        int row = idx >> 6, seg = idx & 63;
        uint32_t dst = sb + row * SAROW + seg * 16;
        const void* src = Wp + row * HDIM + seg * 8;
        asm volatile("cp.async.cg.shared.global [%0], [%1], 16;" :: "r"(dst), "l"(src));
    }
    asm volatile("cp.async.commit_group;" ::: "memory");

    int b = tid & 31, ul = tid >> 5;             // one (unit, batch) per thread
    int u = jt * 16 + ul;
    float creg = c0[b * HDIM + u];
    float hlast = 0.0f;

    float* gS0 = (float*)(sm + SMG);
    float* gS1 = gS0 + 64 * 33;
    int wg = w >> 3, wq = w & 7;                 // wg: kk half; wq: 4m x 2n
    int wm = wq >> 1, wn = wq & 1;

    for (int t = 0; t < TD; t++) {
        const float* xp = g_xihp + ((size_t)t * G4 + u * 4) * 32 + b;
        float x0 = xp[0], x1 = xp[32], x2 = xp[64], x3 = xp[96];

        const __half* hp = g_hsh + (size_t)t * BSZ * HDIM;
#pragma unroll
        for (int p = 0; p < 4; p++) {            // 2048 segs: 32 rows x 64
            int idx = p * 512 + tid;
            int row = idx >> 6, seg = idx & 63;
            uint32_t dst = sb + SMH + row * SAROW + seg * 16;
            const void* src = hp + row * HDIM + seg * 8;
            asm volatile("cp.async.cg.shared.global [%0], [%1], 16;" :: "r"(dst), "l"(src));
        }
        asm volatile("cp.async.commit_group;" ::: "memory");
        asm volatile("cp.async.wait_group 0;" ::: "memory");
        __syncthreads();

        float acc[2][4] = {};
#pragma unroll
        for (int kk2 = 0; kk2 < 16; kk2++) {
            int kk = wg * 16 + kk2;
            uint32_t a[4], bb[4];
            {
                int row = wm * 16 + (lane & 15);
                int ko = kk * 16 + ((lane >> 4) << 3);
                uint32_t ad = sb + row * SAROW + ko * 2;
                asm volatile("ldmatrix.sync.aligned.m8n8.x4.shared.b16 {%0,%1,%2,%3}, [%4];"
                             : "=r"(a[0]), "=r"(a[1]), "=r"(a[2]), "=r"(a[3]) : "r"(ad));
            }
            {
                int nrow = wn * 16 + (lane & 7) + (((lane >> 4) & 1) << 3);
                int ko = kk * 16 + (((lane >> 3) & 1) << 3);
                uint32_t bd = sb + SMH + nrow * SAROW + ko * 2;
                asm volatile("ldmatrix.sync.aligned.m8n8.x4.shared.b16 {%0,%1,%2,%3}, [%4];"
                             : "=r"(bb[0]), "=r"(bb[1]), "=r"(bb[2]), "=r"(bb[3]) : "r"(bd));
            }
#pragma unroll
            for (int s = 0; s < 2; s++) {
                asm volatile(
                    "mma.sync.aligned.m16n8k16.row.col.f32.f16.f16.f32 "
                    "{%0,%1,%2,%3}, {%4,%5,%6,%7}, {%8,%9}, {%0,%1,%2,%3};"
                    : "+f"(acc[s][0]), "+f"(acc[s][1]), "+f"(acc[s][2]), "+f"(acc[s][3])
                    : "r"(a[0]), "r"(a[1]), "r"(a[2]), "r"(a[3]),
                      "r"(bb[2*s]), "r"(bb[2*s+1]));
            }
        }
        {
            float* gD = wg ? gS1 : gS0;
            int r0 = wm * 16 + (lane >> 2);
#pragma unroll
            for (int s = 0; s < 2; s++) {
                int c0i = wn * 16 + s * 8 + 2 * (lane & 3);
                gD[r0 * 33 + c0i]           = acc[s][0];
                gD[r0 * 33 + c0i + 1]       = acc[s][1];
                gD[(r0 + 8) * 33 + c0i]     = acc[s][2];
                gD[(r0 + 8) * 33 + c0i + 1] = acc[s][3];
            }
        }
        __syncthreads();

        {
            float gi = gS0[(4 * ul + 0) * 33 + b] + gS1[(4 * ul + 0) * 33 + b] + x0;
            float gf = gS0[(4 * ul + 1) * 33 + b] + gS1[(4 * ul + 1) * 33 + b] + x1;
            float gg = gS0[(4 * ul + 2) * 33 + b] + gS1[(4 * ul + 2) * 33 + b] + x2;
            float go = gS0[(4 * ul + 3) * 33 + b] + gS1[(4 * ul + 3) * 33 + b] + x3;
            float c = sigf(gf) * creg + sigf(gi) * tanhf(gg);
            creg = c;
            float hh = sigf(go) * tanhf(c);
            hlast = hh;
            g_hsh[((size_t)(t + 1) * BSZ + b) * HDIM + u] = __float2half(hh);
        }

        __syncthreads();
        if (tid == 0) {
            asm volatile("red.release.gpu.global.add.u32 [%0], %1;"
                         :: "l"(&g_bar), "r"(1u) : "memory");
            unsigned target = (unsigned)(t + 1) * LCTA;
            unsigned v;
            do {
                asm volatile("ld.relaxed.gpu.global.u32 %0, [%1];"
                             : "=r"(v) : "l"(&g_bar) : "memory");
            } while (v < target);
            asm volatile("ld.acquire.gpu.global.u32 %0, [%1];"
                         : "=r"(v) : "l"(&g_bar) : "memory");
        }
        __syncthreads();
    }

    g_c[b * HDIM + u] = creg;
    out[(size_t)M_BT * VOC + b * HDIM + u] = hlast;
    out[(size_t)M_BT * VOC + BSZ * HDIM + b * HDIM + u] = creg;
}

// ---------------------------------------------------------------------------
// HMMA attention (unchanged)
__global__ __launch_bounds__(256, 1)
void k_attn2() {
    extern __shared__ char sm[];
    uint32_t sb = smem_u32(sm);
    int tid = threadIdx.x, wid = tid >> 5, lane = tid & 31;
    int bi = blockIdx.x;
    int b = bi >> 1, t0 = (bi & 1) * 32;

    const __half* encp = g_ench + (size_t)b * TEC * HDIM;
#pragma unroll
    for (int p = 0; p < 32; p++) {
        int idx = p * 256 + tid;
        int row = idx >> 6, seg = idx & 63;
        uint32_t dst = sb + AT_ENC + row * SAROW + seg * 16;
        const void* src = encp + (size_t)row * HDIM + seg * 8;
        asm volatile("cp.async.cg.shared.global [%0], [%1], 16;" :: "r"(dst), "l"(src));
    }
#pragma unroll
    for (int p = 0; p < 8; p++) {
        int idx = p * 256 + tid;
        int row = idx >> 6, seg = idx & 63;
        uint32_t dst = sb + AT_H + row * SAROW + seg * 16;
        const void* src = g_hsh + ((size_t)(t0 + row + 1) * BSZ + b) * HDIM + seg * 8;
        asm volatile("cp.async.cg.shared.global [%0], [%1], 16;" :: "r"(dst), "l"(src));
    }
    asm volatile("cp.async.commit_group;" ::: "memory");
    asm volatile("cp.async.wait_group 0;" ::: "memory");
    __syncthreads();

    int wm2 = wid >> 2, wn2 = wid & 3;

    float sacc[2][2][4] = {};
#pragma unroll
    for (int kk = 0; kk < 32; kk++) {
        uint32_t a[4];
        {
            int row = wm2 * 16 + (lane & 15);
            int ko = kk * 16 + ((lane >> 4) << 3);
            uint32_t ad = sb + AT_H + row * SAROW + ko * 2;
            asm volatile("ldmatrix.sync.aligned.m8n8.x4.shared.b16 {%0,%1,%2,%3}, [%4];"
                         : "=r"(a[0]), "=r"(a[1]), "=r"(a[2]), "=r"(a[3]) : "r"(ad));
        }
#pragma unroll
        for (int j2 = 0; j2 < 2; j2++) {
            uint32_t bb[4];
            int nrow = wn2 * 32 + j2 * 16 + (lane & 7) + (((lane >> 4) & 1) << 3);
            int ko = kk * 16 + (((lane >> 3) & 1) << 3);
            uint32_t bd = sb + AT_ENC + nrow * SAROW + ko * 2;
            asm volatile("ldmatrix.sync.aligned.m8n8.x4.shared.b16 {%0,%1,%2,%3}, [%4];"
                         : "=r"(bb[0]), "=r"(bb[1]), "=r"(bb[2]), "=r"(bb[3]) : "r"(bd));
#pragma unroll
            for (int s = 0; s < 2; s++) {
                asm volatile(
                    "mma.sync.aligned.m16n8k16.row.col.f32.f16.f16.f32 "
                    "{%0,%1,%2,%3}, {%4,%5,%6,%7}, {%8,%9}, {%0,%1,%2,%3};"
                    : "+f"(sacc[j2][s][0]), "+f"(sacc[j2][s][1]),
                      "+f"(sacc[j2][s][2]), "+f"(sacc[j2][s][3])
                    : "r"(a[0]), "r"(a[1]), "r"(a[2]), "r"(a[3]),
                      "r"(bb[2*s]), "r"(bb[2*s+1]));
            }
        }
    }
    float* sc = (float*)(sm + AT_SC);
    {
        int r0 = wm2 * 16 + (lane >> 2);
#pragma unroll
        for (int j2 = 0; j2 < 2; j2++)
#pragma unroll
            for (int nb = 0; nb < 2; nb++) {
                int c0i = wn2 * 32 + j2 * 16 + nb * 8 + 2 * (lane & 3);
                sc[r0 * 132 + c0i]           = sacc[j2][nb][0];
                sc[r0 * 132 + c0i + 1]       = sacc[j2][nb][1];
                sc[(r0 + 8) * 132 + c0i]     = sacc[j2][nb][2];
                sc[(r0 + 8) * 132 + c0i + 1] = sacc[j2][nb][3];
            }
    }
    __syncthreads();

    __half* Pp = (__half*)(sm + AT_P);
#pragma unroll
    for (int r = 0; r < 4; r++) {
        int row = wid * 4 + r;
        float sv[4], mx = -1e30f;
#pragma unroll
        for (int q = 0; q < 4; q++) { sv[q] = sc[row * 132 + lane + 32 * q]; mx = fmaxf(mx, sv[q]); }
#pragma unroll
        for (int off = 16; off; off >>= 1) mx = fmaxf(mx, __shfl_xor_sync(0xffffffffu, mx, off));
        float sum = 0.0f;
#pragma unroll
        for (int q = 0; q < 4; q++) { sv[q] = expf(sv[q] - mx); sum += sv[q]; }
#pragma unroll
        for (int off = 16; off; off >>= 1) sum += __shfl_xor_sync(0xffffffffu, sum, off);
        float inv = 1.0f / sum;
#pragma unroll
        for (int q = 0; q < 4; q++)
            Pp[row * 136 + lane + 32 * q] = __float2half(sv[q] * inv);
    }
    __syncthreads();

    float cacc[8][2][4];
#pragma unroll
    for (int j2 = 0; j2 < 8; j2++)
#pragma unroll
        for (int nb = 0; nb < 2; nb++)
#pragma unroll
            for (int q = 0; q < 4; q++) cacc[j2][nb][q] = 0.0f;

#pragma unroll
    for (int kk = 0; kk < 8; kk++) {
        uint32_t a[4];
        {
            int row = wm2 * 16 + (lane & 15);
            int ko = kk * 16 + ((lane >> 4) << 3);
            uint32_t ad = sb + AT_P + row * 272 + ko * 2;
            asm volatile("ldmatrix.sync.aligned.m8n8.x4.shared.b16 {%0,%1,%2,%3}, [%4];"
                         : "=r"(a[0]), "=r"(a[1]), "=r"(a[2]), "=r"(a[3]) : "r"(ad));
        }
#pragma unroll
        for (int j2 = 0; j2 < 8; j2++) {
            uint32_t bb[4];
            int j0 = wn2 * 128 + j2 * 16;
            int te = kk * 16 + (((lane >> 3) & 1) << 3) + (lane & 7);
            int jc = j0 + (((lane >> 4) & 1) << 3);
            uint32_t bd = sb + AT_ENC + te * SAROW + jc * 2;
            asm volatile("ldmatrix.sync.aligned.m8n8.x4.trans.shared.b16 {%0,%1,%2,%3}, [%4];"
                         : "=r"(bb[0]), "=r"(bb[1]), "=r"(bb[2]), "=r"(bb[3]) : "r"(bd));
#pragma unroll
            for (int s = 0; s < 2; s++) {
                asm volatile(
                    "mma.sync.aligned.m16n8k16.row.col.f32.f16.f16.f32 "
                    "{%0,%1,%2,%3}, {%4,%5,%6,%7}, {%8,%9}, {%0,%1,%2,%3};"
                    : "+f"(cacc[j2][s][0]), "+f"(cacc[j2][s][1]),
                      "+f"(cacc[j2][s][2]), "+f"(cacc[j2][s][3])
                    : "r"(a[0]), "r"(a[1]), "r"(a[2]), "r"(a[3]),
                      "r"(bb[2*s]), "r"(bb[2*s+1]));
            }
        }
    }

    {
        int r0 = wm2 * 16 + (lane >> 2);
#pragma unroll
        for (int j2 = 0; j2 < 8; j2++)
#pragma unroll
            for (int nb = 0; nb < 2; nb++) {
                int c0i = wn2 * 128 + j2 * 16 + nb * 8 + 2 * (lane & 3);
                int m = b * TD + t0 + r0;
                *(__half2*)(g_cath + (size_t)m * (2 * HDIM) + HDIM + c0i) =
                    __floats2half2_rn(cacc[j2][nb][0], cacc[j2][nb][1]);
                *(__half2*)(g_cath + (size_t)(m + 8) * (2 * HDIM) + HDIM + c0i) =
                    __floats2half2_rn(cacc[j2][nb][2], cacc[j2][nb][3]);
            }
    }
#pragma unroll
    for (int p = 0; p < 8; p++) {
        int idx = p * 256 + tid;
        int row = idx >> 6, seg = idx & 63;
        uint4 v = *(uint4*)(sm + AT_H + row * SAROW + seg * 16);
        int m = b * TD + t0 + row;
        *(uint4*)(g_cath + (size_t)m * (2 * HDIM) + seg * 8) = v;
    }
}

// ---------------------------------------------------------------------------
extern "C" void kernel_launch(void* const* d_in, const int* in_sizes, int n_in,
                              void* d_out, int out_size) {
    const int*   decX = (const int*)d_in[0];
    const float* enc  = (const float*)d_in[1];
    const float* h0   = (const float*)d_in[2];
    const float* c0   = (const float*)d_in[3];
    const float* embW = (const float*)d_in[4];
    const float* Wih  = (const float*)d_in[5];
    const float* Whh  = (const float*)d_in[6];
    const float* bih  = (const float*)d_in[7];
    const float* bhh  = (const float*)d_in[8];
    const float* attW = (const float*)d_in[9];
    const float* attb = (const float*)d_in[10];
    const float* fcW  = (const float*)d_in[11];
    const float* fcb  = (const float*)d_in[12];
    float* out = (float*)d_out;

    __half *p_Wihh, *p_attWh, *p_embh, *p_cath, *p_Ah, *p_Bh;
    float *p_bias;
    cudaGetSymbolAddress((void**)&p_Wihh,  g_Wihh);
    cudaGetSymbolAddress((void**)&p_attWh, g_attWh);
    cudaGetSymbolAddress((void**)&p_embh,  g_embh);
    cudaGetSymbolAddress((void**)&p_cath,  g_cath);
    cudaGetSymbolAddress((void**)&p_Ah,    g_Ah);
    cudaGetSymbolAddress((void**)&p_Bh,    g_Bh);
    cudaGetSymbolAddress((void**)&p_bias,  g_bias);

    cudaFuncSetAttribute(k_hgemm2, cudaFuncAttributeMaxDynamicSharedMemorySize, SM_TOTAL);
    cudaFuncSetAttribute(k_lstm_p, cudaFuncAttributeMaxDynamicSharedMemorySize, STEP_SMEM);
    cudaFuncSetAttribute(k_attn2,  cudaFuncAttributeMaxDynamicSharedMemorySize, ATN_SMEM);

    k_init<<<NB_INIT, 256>>>(Wih, Whh, bih, bhh, h0, decX, embW);
    k_hgemm2<<<dim3(M_BT / BM, G4 / BN), 256, SM_TOTAL>>>(
        p_embh, p_Wihh, p_bias, nullptr, EDIM, EDIM / BK, 0, 0);
    // Persistent LSTM (32 CTAs x 512 thr) + hidden conversions (116 CTAs)
    k_lstm_p<<<TOTCTA, 512, STEP_SMEM>>>(c0, out, fcW, attW, enc);
    k_attn2<<<64, 256, ATN_SMEM>>>();
    k_hgemm2<<<dim3(M_BT / BM, HDIM / BN), 256, SM_TOTAL>>>(
        p_cath, p_attWh, attb, nullptr, 2 * HDIM, 2 * HDIM / BK, 0, 1);
    k_hgemm2<<<dim3(M_BT / BM, VOC / BN), 256, SM_TOTAL>>>(
        p_Ah, p_Bh, fcb, out, KDIM, KDIM / BK, VOC, 2);
}